// round 16
// baseline (speedup 1.0000x reference)
#include <cuda_runtime.h>
#include <cuda_fp16.h>
#include <math.h>
#include <stdint.h>

// Shapes (fixed by dataset)
#define BROWS 16384
#define DDIM  2048
#define EEXP  64

// Tiling (R8-proven optimum)
#define BM 128
#define BK 32              // K per chunk (2 x k16 mma steps)
#define NCHUNK (DDIM / BK) // 64
#define NTHREADS 512
#define LDAH 40            // smem row stride in halves (80B rows)
#define LDLOG 132          // epilogue logits row stride (floats)

// smem stage layout (halves): Ah | Al | Bh | Bl, each [128][LDAH]
#define MAT_HALVES  (128 * LDAH)          // 5120
#define AH_OFF 0
#define AL_OFF (1 * MAT_HALVES)
#define BH_OFF (2 * MAT_HALVES)
#define BL_OFF (3 * MAT_HALVES)
#define STAGE_HALVES (4 * MAT_HALVES)     // 20480
#define STAGE_BYTES  (STAGE_HALVES * 2)
#define SMEM_BYTES   (2 * STAGE_BYTES)    // 81920 (>= 128*LDLOG*4 = 67584 for epilogue)

// pre-split weights: row j in [0,128) = (j<64 ? gate[j] : noise[j-64]), packed fp16
__device__ __half WHI[(size_t)128 * DDIM];
__device__ __half WLO[(size_t)128 * DDIM];

// m16n8k16 fp16 mma, fp32 accum
#define MMA_F16(c, a, b) \
    asm volatile("mma.sync.aligned.m16n8k16.row.col.f32.f16.f16.f32 " \
                 "{%0,%1,%2,%3}, {%4,%5,%6,%7}, {%8,%9}, {%0,%1,%2,%3};" \
                 : "+f"((c)[0]), "+f"((c)[1]), "+f"((c)[2]), "+f"((c)[3]) \
                 : "r"((a)[0]), "r"((a)[1]), "r"((a)[2]), "r"((a)[3]), \
                   "r"((b)[0]), "r"((b)[1]))

#define LDMX4(r0, r1, r2, r3, addr) \
    asm volatile("ldmatrix.sync.aligned.m8n8.x4.shared.b16 {%0,%1,%2,%3}, [%4];" \
                 : "=r"(r0), "=r"(r1), "=r"(r2), "=r"(r3) : "r"(addr))

// .cg: bypass L1 fill for the stream-once B weights (L2-resident across CTAs)
#define CP_ASYNC16(dst, src) \
    asm volatile("cp.async.cg.shared.global [%0], [%1], 16;" \
                 :: "r"(dst), "l"(__cvta_generic_to_global(src)))
#define CP_COMMIT() asm volatile("cp.async.commit_group;" ::: "memory")
#define CP_WAIT0()  asm volatile("cp.async.wait_group 0;" ::: "memory")

__device__ __forceinline__ uint32_t smem_u32(const void* p) {
    uint32_t a;
    asm("{ .reg .u64 t; cvta.to.shared.u64 t, %1; cvt.u32.u64 %0, t; }" : "=r"(a) : "l"(p));
    return a;
}
__device__ __forceinline__ void split2(float a, float b, uint32_t& h2, uint32_t& l2) {
    __half ha = __float2half_rn(a), hb = __float2half_rn(b);
    float  ra = __half2float(ha),  rb = __half2float(hb);
    __half la = __float2half_rn(a - ra), lb = __float2half_rn(b - rb);
    h2 = (uint32_t)__half_as_ushort(ha) | ((uint32_t)__half_as_ushort(hb) << 16);
    l2 = (uint32_t)__half_as_ushort(la) | ((uint32_t)__half_as_ushort(lb) << 16);
}
__device__ __forceinline__ void split8(float4 v0, float4 v1, uint4& H, uint4& L) {
    split2(v0.x, v0.y, H.x, L.x);
    split2(v0.z, v0.w, H.y, L.y);
    split2(v1.x, v1.y, H.z, L.z);
    split2(v1.z, v1.w, H.w, L.w);
}
__device__ __forceinline__ float softplus_stable(float z) {
    return fmaxf(z, 0.f) + log1pf(expf(-fabsf(z)));
}

// ===== pre-kernel: split weights into fp16 hi/lo =====
__global__ __launch_bounds__(512)
void sg_wsplit(const float* __restrict__ gw, const float* __restrict__ nw)
{
    cudaTriggerProgrammaticLaunchCompletion();

    const int gid = blockIdx.x * 512 + threadIdx.x;   // 65536 threads, 4 floats each
    const int idx = gid * 4;
    const int row = idx >> 11;                        // 0..127
    const int k   = idx & 2047;
    const float* src = (row < 64) ? (gw + (size_t)row * DDIM + k)
                                  : (nw + (size_t)(row - 64) * DDIM + k);
    float4 v = *(const float4*)src;
    uint32_t h0, l0, h1, l1;
    split2(v.x, v.y, h0, l0);
    split2(v.z, v.w, h1, l1);
    *(uint2*)(WHI + idx) = make_uint2(h0, h1);
    *(uint2*)(WLO + idx) = make_uint2(l0, l1);
}

// ===== main fused kernel =====
__global__ __launch_bounds__(NTHREADS, 1)
void sg_fused(const float* __restrict__ x,
              const float* __restrict__ noise,
              float* __restrict__ out)
{
    extern __shared__ __align__(16) char smem_raw[];
    __half* smh = (__half*)smem_raw;
    float*  smf = (float*)smem_raw;
    const uint32_t sbase = smem_u32(smem_raw);

    const int tid  = threadIdx.x;
    const int wid  = tid >> 5;
    const int lane = tid & 31;
    const int m0   = blockIdx.x * BM;

    // 16 warps as 4x4 grid of 32x32 warp tiles
    const int m_warp = (wid & 3) * 32;
    const int n_warp = (wid >> 2) * 32;

    // A loader: thread -> one A row, 8 consecutive k values
    const int lrow = tid >> 2;        // 0..127
    const int lk   = (tid & 3) * 8;   // 0,8,16,24
    const float* aptr = x + (size_t)(m0 + lrow) * DDIM + lk;

    // B cp.async mapping: thread -> 16B segment (8 halves)
    const int brow = tid >> 2;        // 0..127
    const int bseg = tid & 3;         // 0..3 (8 halves each)
    const __half* whsrc = WHI + (size_t)brow * DDIM + bseg * 8;
    const __half* wlsrc = WLO + (size_t)brow * DDIM + bseg * 8;
    const uint32_t bdst = (uint32_t)(brow * LDAH + bseg * 8) * 2;  // byte off in matrix

    // ldmatrix per-lane address components
    const int g  = lane >> 3;          // 0..3 -> dst reg
    const int lr = lane & 7;
    const uint32_t a_rowb = m_warp + (g & 1) * 8 + lr;
    const uint32_t a_colb = (g >> 1) * 8;
    const uint32_t b_rowb = n_warp + (g >> 1) * 8 + lr;
    const uint32_t b_colb = (g & 1) * 8;

    float acc[2][4][4];
#pragma unroll
    for (int mt = 0; mt < 2; ++mt)
#pragma unroll
        for (int nt = 0; nt < 4; ++nt)
#pragma unroll
            for (int r = 0; r < 4; ++r) acc[mt][nt][r] = 0.f;

    // ---- stage chunk 0 ----
    // A path first (independent of sg_wsplit): overlaps with the producer kernel
    {
        float4 va0 = *(const float4*)(aptr);
        float4 va1 = *(const float4*)(aptr + 4);
        uint4 H, L;
        split8(va0, va1, H, L);
        *(uint4*)&smh[AH_OFF + lrow * LDAH + lk] = H;
        *(uint4*)&smh[AL_OFF + lrow * LDAH + lk] = L;

        cudaGridDependencySynchronize();

        const uint32_t d0 = sbase + bdst;
        CP_ASYNC16(d0 + BH_OFF * 2, whsrc);
        CP_ASYNC16(d0 + BL_OFF * 2, wlsrc);
        CP_COMMIT();
        CP_WAIT0();
    }
    __syncthreads();

    float4 va0, va1;
    int cur = 0;
    for (int t = 0; t < NCHUNK; ++t) {
        const bool have_next = (t + 1 < NCHUNK);
        const int  nxt = cur ^ 1;
        if (have_next) {
            // issue next B copy immediately (overlaps compute below)
            const uint32_t dn = sbase + nxt * STAGE_BYTES + bdst;
            const int off = (t + 1) * BK;
            CP_ASYNC16(dn + BH_OFF * 2, whsrc + off);
            CP_ASYNC16(dn + BL_OFF * 2, wlsrc + off);
            CP_COMMIT();
            va0 = *(const float4*)(aptr + off);
            va1 = *(const float4*)(aptr + off + 4);
        }

        const uint32_t sb = sbase + cur * STAGE_BYTES;

#pragma unroll
        for (int k16 = 0; k16 < 2; ++k16) {
            const uint32_t kb = k16 * 16;
            const uint32_t aoff = sb + (uint32_t)(a_rowb * LDAH + a_colb + kb) * 2;
            const uint32_t boff = sb + (uint32_t)(b_rowb * LDAH + b_colb + kb) * 2;

            uint32_t ah[2][4], al[2][4], bh[4][2], bl[4][2];
#pragma unroll
            for (int mt = 0; mt < 2; ++mt) {
                const uint32_t ao = aoff + (uint32_t)(mt * 16 * LDAH) * 2;
                LDMX4(ah[mt][0], ah[mt][1], ah[mt][2], ah[mt][3], ao + AH_OFF * 2);
                LDMX4(al[mt][0], al[mt][1], al[mt][2], al[mt][3], ao + AL_OFF * 2);
            }
#pragma unroll
            for (int p = 0; p < 2; ++p) {
                const uint32_t bo = boff + (uint32_t)(p * 16 * LDAH) * 2;
                LDMX4(bh[2*p][0], bh[2*p][1], bh[2*p+1][0], bh[2*p+1][1], bo + BH_OFF * 2);
                LDMX4(bl[2*p][0], bl[2*p][1], bl[2*p+1][0], bl[2*p+1][1], bo + BL_OFF * 2);
            }
            // 3 split passes: hh, hl, lh
#pragma unroll
            for (int mt = 0; mt < 2; ++mt)
#pragma unroll
                for (int nt = 0; nt < 4; ++nt)
                    MMA_F16(acc[mt][nt], ah[mt], bh[nt]);
#pragma unroll
            for (int mt = 0; mt < 2; ++mt)
#pragma unroll
                for (int nt = 0; nt < 4; ++nt)
                    MMA_F16(acc[mt][nt], ah[mt], bl[nt]);
#pragma unroll
            for (int mt = 0; mt < 2; ++mt)
#pragma unroll
                for (int nt = 0; nt < 4; ++nt)
                    MMA_F16(acc[mt][nt], al[mt], bh[nt]);
        }

        if (have_next) {
            __half* SN = smh + nxt * STAGE_HALVES;
            uint4 H, L;
            split8(va0, va1, H, L);
            *(uint4*)&SN[AH_OFF + lrow * LDAH + lk] = H;
            *(uint4*)&SN[AL_OFF + lrow * LDAH + lk] = L;
            CP_WAIT0();
            __syncthreads();
            cur = nxt;
        }
    }

    // ===== epilogue: exchange logits through smem, fused gate (ALL 512 threads) =====
    __syncthreads();   // all reads of stage buffers done; smem reused for logits
    const int frow = lane >> 2;
    const int fcol = lane & 3;
#pragma unroll
    for (int mt = 0; mt < 2; ++mt) {
        const int r0 = m_warp + mt * 16 + frow;
#pragma unroll
        for (int nt = 0; nt < 4; ++nt) {
            const int col = n_warp + nt * 8 + fcol * 2;
            *(float2*)&smf[(r0)     * LDLOG + col] = make_float2(acc[mt][nt][0], acc[mt][nt][1]);
            *(float2*)&smf[(r0 + 8) * LDLOG + col] = make_float2(acc[mt][nt][2], acc[mt][nt][3]);
        }
    }

    // 4 lanes per row: row = tid>>2, each lane owns experts [sub*16, sub*16+16)
    const int erow = tid >> 2;          // 0..127
    const int sub  = tid & 3;           // 0..3
    const int rowg = m0 + erow;

    // prefetch this lane's noise slice BEFORE the barrier (hides DRAM latency)
    float4 nzv[4];
    {
        const float4* nzp = (const float4*)(noise + (size_t)rowg * EEXP + sub * 16);
#pragma unroll
        for (int j = 0; j < 4; ++j) nzv[j] = nzp[j];
    }
    __syncthreads();

    {
        const float* lg = smf + erow * LDLOG;

        float v1 = -INFINITY, v2 = -INFINITY;
        int   i1 = -1, i2 = -1;
#pragma unroll
        for (int gq = 0; gq < 4; ++gq) {
            const int   e0 = sub * 16 + 4 * gq;
            const float4 c = *(const float4*)(lg + e0);
            const float4 s = *(const float4*)(lg + 64 + e0);
            const float4 n = nzv[gq];
            float ev[4];
            ev[0] = c.x + n.x * softplus_stable(s.x);
            ev[1] = c.y + n.y * softplus_stable(s.y);
            ev[2] = c.z + n.z * softplus_stable(s.z);
            ev[3] = c.w + n.w * softplus_stable(s.w);
#pragma unroll
            for (int c4 = 0; c4 < 4; ++c4) {
                const float v = ev[c4];
                const int   e = e0 + c4;
                if (v > v1)      { v2 = v1; i2 = i1; v1 = v; i1 = e; }
                else if (v > v2) { v2 = v;  i2 = e; }
            }
        }

        // merge top-2 across the 4 lanes of this row (lanes differ in bits 0..1)
#pragma unroll
        for (int d = 1; d <= 2; d <<= 1) {
            const float ov1 = __shfl_xor_sync(0xFFFFFFFFu, v1, d);
            const int   oi1 = __shfl_xor_sync(0xFFFFFFFFu, i1, d);
            const float ov2 = __shfl_xor_sync(0xFFFFFFFFu, v2, d);
            const int   oi2 = __shfl_xor_sync(0xFFFFFFFFu, i2, d);
            if (ov1 > v1)      { v2 = v1; i2 = i1; v1 = ov1; i1 = oi1; }
            else if (ov1 > v2) { v2 = ov1; i2 = oi1; }
            if (ov2 > v2)      { v2 = ov2; i2 = oi2; }
        }

        const float ex = expf(v2 - v1);
        const float p1 = 1.f / (1.f + ex);
        const float p2 = 1.f - p1;

        float* o = out + (size_t)rowg * EEXP + sub * 16;
#pragma unroll
        for (int gq = 0; gq < 4; ++gq) {
            const int e = sub * 16 + 4 * gq;
            float4 v;
            v.x = (e     == i1) ? p1 : ((e     == i2) ? p2 : 0.f);
            v.y = (e + 1 == i1) ? p1 : ((e + 1 == i2) ? p2 : 0.f);
            v.z = (e + 2 == i1) ? p1 : ((e + 2 == i2) ? p2 : 0.f);
            v.w = (e + 3 == i1) ? p1 : ((e + 3 == i2) ? p2 : 0.f);
            *(float4*)(o + 4 * gq) = v;
        }
    }
}

extern "C" void kernel_launch(void* const* d_in, const int* in_sizes, int n_in,
                              void* d_out, int out_size)
{
    const float* x     = (const float*)d_in[0];
    const float* gw    = (const float*)d_in[1];
    const float* nw    = (const float*)d_in[2];
    const float* noise = (const float*)d_in[3];
    // d_in[4] is k (=2), compile-time constant

    sg_wsplit<<<128, 512>>>(gw, nw);

    cudaFuncSetAttribute(sg_fused, cudaFuncAttributeMaxDynamicSharedMemorySize, SMEM_BYTES);

    cudaLaunchConfig_t cfg = {};
    cfg.gridDim  = dim3(BROWS / BM);
    cfg.blockDim = dim3(NTHREADS);
    cfg.dynamicSmemBytes = SMEM_BYTES;
    cfg.stream = 0;
    cudaLaunchAttribute attrs[1];
    attrs[0].id = cudaLaunchAttributeProgrammaticStreamSerialization;
    attrs[0].val.programmaticStreamSerializationAllowed = 1;
    cfg.attrs = attrs;
    cfg.numAttrs = 1;
    cudaLaunchKernelEx(&cfg, sg_fused, x, noise, (float*)d_out);
}

// round 17
// speedup vs baseline: 1.0543x; 1.0543x over previous
#include <cuda_runtime.h>
#include <cuda_fp16.h>
#include <math.h>
#include <stdint.h>

// Shapes (fixed by dataset)
#define BROWS 16384
#define DDIM  2048
#define EEXP  64

// Tiling (R8-proven optimum)
#define BM 128
#define BK 32              // K per chunk (2 x k16 mma steps)
#define NCHUNK (DDIM / BK) // 64
#define NTHREADS 512
#define LDAH 40            // smem row stride in halves (80B rows)
#define LDLOG 132          // epilogue logits row stride (floats)

// smem stage layout (halves): Ah | Al | Bh | Bl, each [128][LDAH]
#define MAT_HALVES  (128 * LDAH)          // 5120
#define AH_OFF 0
#define AL_OFF (1 * MAT_HALVES)
#define BH_OFF (2 * MAT_HALVES)
#define BL_OFF (3 * MAT_HALVES)
#define STAGE_HALVES (4 * MAT_HALVES)     // 20480
#define STAGE_BYTES  (STAGE_HALVES * 2)
#define SMEM_BYTES   (2 * STAGE_BYTES)    // 81920 (>= 128*LDLOG*4 = 67584 for epilogue)

// pre-split weights: row j in [0,128) = (j<64 ? gate[j] : noise[j-64]), packed fp16
__device__ __half WHI[(size_t)128 * DDIM];
__device__ __half WLO[(size_t)128 * DDIM];

// m16n8k16 fp16 mma, fp32 accum
#define MMA_F16(c, a, b) \
    asm volatile("mma.sync.aligned.m16n8k16.row.col.f32.f16.f16.f32 " \
                 "{%0,%1,%2,%3}, {%4,%5,%6,%7}, {%8,%9}, {%0,%1,%2,%3};" \
                 : "+f"((c)[0]), "+f"((c)[1]), "+f"((c)[2]), "+f"((c)[3]) \
                 : "r"((a)[0]), "r"((a)[1]), "r"((a)[2]), "r"((a)[3]), \
                   "r"((b)[0]), "r"((b)[1]))

#define LDMX4(r0, r1, r2, r3, addr) \
    asm volatile("ldmatrix.sync.aligned.m8n8.x4.shared.b16 {%0,%1,%2,%3}, [%4];" \
                 : "=r"(r0), "=r"(r1), "=r"(r2), "=r"(r3) : "r"(addr))

// .ca (R8-proven; .cg regressed the mainloop in R16)
#define CP_ASYNC16(dst, src) \
    asm volatile("cp.async.ca.shared.global [%0], [%1], 16;" \
                 :: "r"(dst), "l"(__cvta_generic_to_global(src)))
#define CP_COMMIT() asm volatile("cp.async.commit_group;" ::: "memory")
#define CP_WAIT0()  asm volatile("cp.async.wait_group 0;" ::: "memory")

__device__ __forceinline__ uint32_t smem_u32(const void* p) {
    uint32_t a;
    asm("{ .reg .u64 t; cvta.to.shared.u64 t, %1; cvt.u32.u64 %0, t; }" : "=r"(a) : "l"(p));
    return a;
}
__device__ __forceinline__ void split2(float a, float b, uint32_t& h2, uint32_t& l2) {
    __half ha = __float2half_rn(a), hb = __float2half_rn(b);
    float  ra = __half2float(ha),  rb = __half2float(hb);
    __half la = __float2half_rn(a - ra), lb = __float2half_rn(b - rb);
    h2 = (uint32_t)__half_as_ushort(ha) | ((uint32_t)__half_as_ushort(hb) << 16);
    l2 = (uint32_t)__half_as_ushort(la) | ((uint32_t)__half_as_ushort(lb) << 16);
}
__device__ __forceinline__ void split8(float4 v0, float4 v1, uint4& H, uint4& L) {
    split2(v0.x, v0.y, H.x, L.x);
    split2(v0.z, v0.w, H.y, L.y);
    split2(v1.x, v1.y, H.z, L.z);
    split2(v1.z, v1.w, H.w, L.w);
}
__device__ __forceinline__ float softplus_stable(float z) {
    return fmaxf(z, 0.f) + log1pf(expf(-fabsf(z)));
}

// ===== pre-kernel: split weights into fp16 hi/lo =====
__global__ __launch_bounds__(512)
void sg_wsplit(const float* __restrict__ gw, const float* __restrict__ nw)
{
    cudaTriggerProgrammaticLaunchCompletion();

    const int gid = blockIdx.x * 512 + threadIdx.x;   // 65536 threads, 4 floats each
    const int idx = gid * 4;
    const int row = idx >> 11;                        // 0..127
    const int k   = idx & 2047;
    const float* src = (row < 64) ? (gw + (size_t)row * DDIM + k)
                                  : (nw + (size_t)(row - 64) * DDIM + k);
    float4 v = *(const float4*)src;
    uint32_t h0, l0, h1, l1;
    split2(v.x, v.y, h0, l0);
    split2(v.z, v.w, h1, l1);
    *(uint2*)(WHI + idx) = make_uint2(h0, h1);
    *(uint2*)(WLO + idx) = make_uint2(l0, l1);
}

// ===== main fused kernel =====
__global__ __launch_bounds__(NTHREADS, 1)
void sg_fused(const float* __restrict__ x,
              const float* __restrict__ noise,
              float* __restrict__ out)
{
    extern __shared__ __align__(16) char smem_raw[];
    __half* smh = (__half*)smem_raw;
    float*  smf = (float*)smem_raw;
    const uint32_t sbase = smem_u32(smem_raw);

    const int tid  = threadIdx.x;
    const int wid  = tid >> 5;
    const int lane = tid & 31;
    const int m0   = blockIdx.x * BM;

    // 16 warps as 4x4 grid of 32x32 warp tiles
    const int m_warp = (wid & 3) * 32;
    const int n_warp = (wid >> 2) * 32;

    // A loader: thread -> one A row, 8 consecutive k values
    const int lrow = tid >> 2;        // 0..127
    const int lk   = (tid & 3) * 8;   // 0,8,16,24
    const float* aptr = x + (size_t)(m0 + lrow) * DDIM + lk;

    // B cp.async mapping: thread -> 16B segment (8 halves)
    const int brow = tid >> 2;        // 0..127
    const int bseg = tid & 3;         // 0..3 (8 halves each)
    const __half* whsrc = WHI + (size_t)brow * DDIM + bseg * 8;
    const __half* wlsrc = WLO + (size_t)brow * DDIM + bseg * 8;
    const uint32_t bdst = (uint32_t)(brow * LDAH + bseg * 8) * 2;  // byte off in matrix

    // ldmatrix per-lane address components
    const int g  = lane >> 3;          // 0..3 -> dst reg
    const int lr = lane & 7;
    const uint32_t a_rowb = m_warp + (g & 1) * 8 + lr;
    const uint32_t a_colb = (g >> 1) * 8;
    const uint32_t b_rowb = n_warp + (g >> 1) * 8 + lr;
    const uint32_t b_colb = (g & 1) * 8;

    float acc[2][4][4];
#pragma unroll
    for (int mt = 0; mt < 2; ++mt)
#pragma unroll
        for (int nt = 0; nt < 4; ++nt)
#pragma unroll
            for (int r = 0; r < 4; ++r) acc[mt][nt][r] = 0.f;

    // ---- stage chunk 0 ----
    // A path first (independent of sg_wsplit): overlaps with the producer kernel
    {
        float4 va0 = *(const float4*)(aptr);
        float4 va1 = *(const float4*)(aptr + 4);
        uint4 H, L;
        split8(va0, va1, H, L);
        *(uint4*)&smh[AH_OFF + lrow * LDAH + lk] = H;
        *(uint4*)&smh[AL_OFF + lrow * LDAH + lk] = L;

        cudaGridDependencySynchronize();

        const uint32_t d0 = sbase + bdst;
        CP_ASYNC16(d0 + BH_OFF * 2, whsrc);
        CP_ASYNC16(d0 + BL_OFF * 2, wlsrc);
        CP_COMMIT();
        CP_WAIT0();
    }
    __syncthreads();

    float4 va0, va1;
    int cur = 0;
    for (int t = 0; t < NCHUNK; ++t) {
        const bool have_next = (t + 1 < NCHUNK);
        const int  nxt = cur ^ 1;
        if (have_next) {
            // issue next B copy immediately (overlaps compute below)
            const uint32_t dn = sbase + nxt * STAGE_BYTES + bdst;
            const int off = (t + 1) * BK;
            CP_ASYNC16(dn + BH_OFF * 2, whsrc + off);
            CP_ASYNC16(dn + BL_OFF * 2, wlsrc + off);
            CP_COMMIT();
            va0 = *(const float4*)(aptr + off);
            va1 = *(const float4*)(aptr + off + 4);
        }

        const uint32_t sb = sbase + cur * STAGE_BYTES;

#pragma unroll
        for (int k16 = 0; k16 < 2; ++k16) {
            const uint32_t kb = k16 * 16;
            const uint32_t aoff = sb + (uint32_t)(a_rowb * LDAH + a_colb + kb) * 2;
            const uint32_t boff = sb + (uint32_t)(b_rowb * LDAH + b_colb + kb) * 2;

            uint32_t ah[2][4], al[2][4], bh[4][2], bl[4][2];
#pragma unroll
            for (int mt = 0; mt < 2; ++mt) {
                const uint32_t ao = aoff + (uint32_t)(mt * 16 * LDAH) * 2;
                LDMX4(ah[mt][0], ah[mt][1], ah[mt][2], ah[mt][3], ao + AH_OFF * 2);
                LDMX4(al[mt][0], al[mt][1], al[mt][2], al[mt][3], ao + AL_OFF * 2);
            }
#pragma unroll
            for (int p = 0; p < 2; ++p) {
                const uint32_t bo = boff + (uint32_t)(p * 16 * LDAH) * 2;
                LDMX4(bh[2*p][0], bh[2*p][1], bh[2*p+1][0], bh[2*p+1][1], bo + BH_OFF * 2);
                LDMX4(bl[2*p][0], bl[2*p][1], bl[2*p+1][0], bl[2*p+1][1], bo + BL_OFF * 2);
            }
            // 3 split passes: hh, hl, lh
#pragma unroll
            for (int mt = 0; mt < 2; ++mt)
#pragma unroll
                for (int nt = 0; nt < 4; ++nt)
                    MMA_F16(acc[mt][nt], ah[mt], bh[nt]);
#pragma unroll
            for (int mt = 0; mt < 2; ++mt)
#pragma unroll
                for (int nt = 0; nt < 4; ++nt)
                    MMA_F16(acc[mt][nt], ah[mt], bl[nt]);
#pragma unroll
            for (int mt = 0; mt < 2; ++mt)
#pragma unroll
                for (int nt = 0; nt < 4; ++nt)
                    MMA_F16(acc[mt][nt], al[mt], bh[nt]);
        }

        if (have_next) {
            __half* SN = smh + nxt * STAGE_HALVES;
            uint4 H, L;
            split8(va0, va1, H, L);
            *(uint4*)&SN[AH_OFF + lrow * LDAH + lk] = H;
            *(uint4*)&SN[AL_OFF + lrow * LDAH + lk] = L;
            CP_WAIT0();
            __syncthreads();
            cur = nxt;
        }
    }

    // ===== epilogue: exchange logits through smem, fused gate (ALL 512 threads) =====
    __syncthreads();   // all reads of stage buffers done; smem reused for logits
    const int frow = lane >> 2;
    const int fcol = lane & 3;
#pragma unroll
    for (int mt = 0; mt < 2; ++mt) {
        const int r0 = m_warp + mt * 16 + frow;
#pragma unroll
        for (int nt = 0; nt < 4; ++nt) {
            const int col = n_warp + nt * 8 + fcol * 2;
            *(float2*)&smf[(r0)     * LDLOG + col] = make_float2(acc[mt][nt][0], acc[mt][nt][1]);
            *(float2*)&smf[(r0 + 8) * LDLOG + col] = make_float2(acc[mt][nt][2], acc[mt][nt][3]);
        }
    }

    // 4 lanes per row: row = tid>>2, each lane owns experts [sub*16, sub*16+16)
    const int erow = tid >> 2;          // 0..127
    const int sub  = tid & 3;           // 0..3
    const int rowg = m0 + erow;

    // prefetch this lane's noise slice BEFORE the barrier (hides DRAM latency)
    float4 nzv[4];
    {
        const float4* nzp = (const float4*)(noise + (size_t)rowg * EEXP + sub * 16);
#pragma unroll
        for (int j = 0; j < 4; ++j) nzv[j] = nzp[j];
    }
    __syncthreads();

    {
        const float* lg = smf + erow * LDLOG;

        float v1 = -INFINITY, v2 = -INFINITY;
        int   i1 = -1, i2 = -1;
#pragma unroll
        for (int gq = 0; gq < 4; ++gq) {
            const int   e0 = sub * 16 + 4 * gq;
            const float4 c = *(const float4*)(lg + e0);
            const float4 s = *(const float4*)(lg + 64 + e0);
            const float4 n = nzv[gq];
            float ev[4];
            ev[0] = c.x + n.x * softplus_stable(s.x);
            ev[1] = c.y + n.y * softplus_stable(s.y);
            ev[2] = c.z + n.z * softplus_stable(s.z);
            ev[3] = c.w + n.w * softplus_stable(s.w);
#pragma unroll
            for (int c4 = 0; c4 < 4; ++c4) {
                const float v = ev[c4];
                const int   e = e0 + c4;
                if (v > v1)      { v2 = v1; i2 = i1; v1 = v; i1 = e; }
                else if (v > v2) { v2 = v;  i2 = e; }
            }
        }

        // merge top-2 across the 4 lanes of this row (lanes differ in bits 0..1)
#pragma unroll
        for (int d = 1; d <= 2; d <<= 1) {
            const float ov1 = __shfl_xor_sync(0xFFFFFFFFu, v1, d);
            const int   oi1 = __shfl_xor_sync(0xFFFFFFFFu, i1, d);
            const float ov2 = __shfl_xor_sync(0xFFFFFFFFu, v2, d);
            const int   oi2 = __shfl_xor_sync(0xFFFFFFFFu, i2, d);
            if (ov1 > v1)      { v2 = v1; i2 = i1; v1 = ov1; i1 = oi1; }
            else if (ov1 > v2) { v2 = ov1; i2 = oi1; }
            if (ov2 > v2)      { v2 = ov2; i2 = oi2; }
        }

        const float ex = expf(v2 - v1);
        const float p1 = 1.f / (1.f + ex);
        const float p2 = 1.f - p1;

        float* o = out + (size_t)rowg * EEXP + sub * 16;
#pragma unroll
        for (int gq = 0; gq < 4; ++gq) {
            const int e = sub * 16 + 4 * gq;
            float4 v;
            v.x = (e     == i1) ? p1 : ((e     == i2) ? p2 : 0.f);
            v.y = (e + 1 == i1) ? p1 : ((e + 1 == i2) ? p2 : 0.f);
            v.z = (e + 2 == i1) ? p1 : ((e + 2 == i2) ? p2 : 0.f);
            v.w = (e + 3 == i1) ? p1 : ((e + 3 == i2) ? p2 : 0.f);
            *(float4*)(o + 4 * gq) = v;
        }
    }
}

extern "C" void kernel_launch(void* const* d_in, const int* in_sizes, int n_in,
                              void* d_out, int out_size)
{
    const float* x     = (const float*)d_in[0];
    const float* gw    = (const float*)d_in[1];
    const float* nw    = (const float*)d_in[2];
    const float* noise = (const float*)d_in[3];
    // d_in[4] is k (=2), compile-time constant

    sg_wsplit<<<128, 512>>>(gw, nw);

    cudaFuncSetAttribute(sg_fused, cudaFuncAttributeMaxDynamicSharedMemorySize, SMEM_BYTES);

    cudaLaunchConfig_t cfg = {};
    cfg.gridDim  = dim3(BROWS / BM);
    cfg.blockDim = dim3(NTHREADS);
    cfg.dynamicSmemBytes = SMEM_BYTES;
    cfg.stream = 0;
    cudaLaunchAttribute attrs[1];
    attrs[0].id = cudaLaunchAttributeProgrammaticStreamSerialization;
    attrs[0].val.programmaticStreamSerializationAllowed = 1;
    cfg.attrs = attrs;
    cfg.numAttrs = 1;
    cudaLaunchKernelEx(&cfg, sg_fused, x, noise, (float*)d_out);
}